// round 1
// baseline (speedup 1.0000x reference)
#include <cuda_runtime.h>

// Problem constants
#define Bsz 8
#define Ssz 20
#define Fsz 200
#define Dsz 2048
#define Tn  20
#define En  128
#define Hn  128
#define CDn 300
#define THn 128
#define Mrows (Bsz*Ssz*Fsz)     // 32000
#define ROWS_PER_B (Ssz*Fsz)    // 4000

// Scratch (no allocations allowed)
__device__ float g_pool[Bsz*Dsz];     // masked sum over (s,f) per (b,d)
__device__ float g_vw3[Bsz*Hn];       // video @ W3
__device__ float g_probs[Bsz*Tn];     // topic softmax probs
__device__ float g_contrib[Tn*Hn];    // topic_emb @ W2

// ---------------------------------------------------------------------------
__global__ void zero_pool_kernel() {
    int i = blockIdx.x * 256 + threadIdx.x;
    if (i < Bsz * Dsz) g_pool[i] = 0.f;
}

// grid (D/256, S, B), 256 threads: sum valid frames into g_pool
__global__ void pool_kernel(const float* __restrict__ batch,
                            const int* __restrict__ seg_len) {
    int b = blockIdx.z, s = blockIdx.y;
    int d = blockIdx.x * 256 + threadIdx.x;
    int len = seg_len[b * Ssz + s];
    const float* p = batch + ((size_t)(b * Ssz + s)) * Fsz * Dsz + d;
    float acc = 0.f;
    int f = 0;
    #pragma unroll 4
    for (; f < len; f++) acc += p[(size_t)f * Dsz];
    atomicAdd(&g_pool[b * Dsz + d], acc);
}

// grid Tn blocks, Hn threads: g_contrib[t][h] = sum_e topic_emb[t][e]*W2[e][h]
__global__ void contrib_kernel(const float* __restrict__ topic_emb,
                               const float* __restrict__ W2) {
    int t = blockIdx.x, h = threadIdx.x;
    float acc = 0.f;
    #pragma unroll 8
    for (int e = 0; e < En; e++) acc += topic_emb[t * En + e] * W2[e * Hn + h];
    g_contrib[t * Hn + h] = acc;
}

// grid Bsz blocks, Hn(=128) threads: video, topic probs, vw3
__global__ void small_kernel(const int* __restrict__ seg_len,
                             const float* __restrict__ concept1,
                             const float* __restrict__ concept2,
                             const float* __restrict__ W_enc,
                             const float* __restrict__ b_enc,
                             const float* __restrict__ Wc1,
                             const float* __restrict__ Wc2,
                             const float* __restrict__ Wt1,
                             const float* __restrict__ bt1,
                             const float* __restrict__ Wt2,
                             const float* __restrict__ bt2,
                             const float* __restrict__ W3) {
    int b = blockIdx.x, h = threadIdx.x;
    __shared__ float video[Hn];
    __shared__ float th[THn];
    __shared__ float logits[Tn];

    // denominator = sum of seg_len over s (mask count), clamped to >=1
    int cnt = 0;
    for (int s = 0; s < Ssz; s++) cnt += seg_len[b * Ssz + s];
    float inv = 1.f / fmaxf((float)cnt, 1.f);

    float acc = b_enc[h];
    #pragma unroll 4
    for (int d = 0; d < Dsz; d++)
        acc += (g_pool[b * Dsz + d] * inv) * W_enc[d * Hn + h];
    #pragma unroll 4
    for (int c = 0; c < CDn; c++)
        acc += concept1[b * CDn + c] * Wc1[c * Hn + h]
             + concept2[b * CDn + c] * Wc2[c * Hn + h];
    video[h] = fmaxf(acc, 0.f);
    __syncthreads();

    float a2 = bt1[h];
    float a3 = 0.f;
    #pragma unroll 8
    for (int k = 0; k < Hn; k++) {
        float v = video[k];
        a2 += v * Wt1[k * THn + h];
        a3 += v * W3[k * Hn + h];
    }
    th[h] = fmaxf(a2, 0.f);
    g_vw3[b * Hn + h] = a3;
    __syncthreads();

    if (h < Tn) {
        float a4 = bt2[h];
        #pragma unroll 8
        for (int k = 0; k < THn; k++) a4 += th[k] * Wt2[k * Tn + h];
        logits[h] = a4;
    }
    __syncthreads();
    if (h == 0) {
        float m = -1e30f;
        for (int t = 0; t < Tn; t++) m = fmaxf(m, logits[t]);
        float ssum = 0.f;
        for (int t = 0; t < Tn; t++) { float e = __expf(logits[t] - m); logits[t] = e; ssum += e; }
        float invs = 1.f / ssum;
        for (int t = 0; t < Tn; t++) g_probs[b * Tn + t] = logits[t] * invs;
    }
}

// ---------------------------------------------------------------------------
// Fused GEMM (batch[32000,2048] @ W1[2048,128]) + topic-loop epilogue.
// BM=128, BN=128, BK=16, 256 threads, 8x8 accumulators per thread.
#define BM 128
#define BN 128
#define BK 16

__global__ __launch_bounds__(256, 2)
void gemm_epilogue_kernel(const float* __restrict__ batch,
                          const float* __restrict__ W1,
                          const float* __restrict__ b1,
                          const float* __restrict__ w_out,
                          const float* __restrict__ b_out_p,
                          float* __restrict__ out,
                          int out_size) {
    __shared__ float As[BK][BM];
    __shared__ float Bs[BK][BN];

    int tid = threadIdx.x;
    int tx = tid & 15;        // n-tile coordinate (8 cols each)
    int ty = tid >> 4;        // m-tile coordinate (8 rows each)
    int m0 = blockIdx.x * BM;

    float acc[8][8];
    #pragma unroll
    for (int i = 0; i < 8; i++)
        #pragma unroll
        for (int j = 0; j < 8; j++) acc[i][j] = 0.f;

    // A-load mapping: 512 float4 per tile; thread does e=tid and e=tid+256
    int arow0 = tid >> 2;            // 0..63
    int akq   = (tid & 3) << 2;      // 0,4,8,12
    // B-load mapping
    int bkr0  = tid >> 5;            // 0..7
    int bcol  = (tid & 31) << 2;     // 0..124

    const float* Abase = batch + (size_t)m0 * Dsz;

    for (int k0 = 0; k0 < Dsz; k0 += BK) {
        // load A tile (transposed into As[k][m])
        {
            float4 v0 = *(const float4*)(Abase + (size_t)arow0 * Dsz + k0 + akq);
            float4 v1 = *(const float4*)(Abase + (size_t)(arow0 + 64) * Dsz + k0 + akq);
            As[akq + 0][arow0] = v0.x; As[akq + 1][arow0] = v0.y;
            As[akq + 2][arow0] = v0.z; As[akq + 3][arow0] = v0.w;
            As[akq + 0][arow0 + 64] = v1.x; As[akq + 1][arow0 + 64] = v1.y;
            As[akq + 2][arow0 + 64] = v1.z; As[akq + 3][arow0 + 64] = v1.w;
        }
        // load B tile (row-major chunk of W1)
        {
            float4 w0 = *(const float4*)(W1 + (size_t)(k0 + bkr0) * Hn + bcol);
            float4 w1 = *(const float4*)(W1 + (size_t)(k0 + bkr0 + 8) * Hn + bcol);
            *(float4*)&Bs[bkr0][bcol]     = w0;
            *(float4*)&Bs[bkr0 + 8][bcol] = w1;
        }
        __syncthreads();

        #pragma unroll
        for (int kk = 0; kk < BK; kk++) {
            float a[8], bb[8];
            #pragma unroll
            for (int i = 0; i < 8; i++) a[i] = As[kk][ty * 8 + i];
            #pragma unroll
            for (int j = 0; j < 8; j++) bb[j] = Bs[kk][tx * 8 + j];
            #pragma unroll
            for (int i = 0; i < 8; i++)
                #pragma unroll
                for (int j = 0; j < 8; j++)
                    acc[i][j] = fmaf(a[i], bb[j], acc[i][j]);
        }
        __syncthreads();
    }

    // ----- Epilogue: base = acc + b1 + vw3[b]; then 20-topic relu/score loop -----
    float b1v[8], wov[8];
    #pragma unroll
    for (int j = 0; j < 8; j++) {
        b1v[j] = b1[tx * 8 + j];
        wov[j] = w_out[tx * 8 + j];
    }
    float bo = b_out_p[0];

    int bidx[8];
    #pragma unroll
    for (int i = 0; i < 8; i++) {
        int row = m0 + ty * 8 + i;
        int b = row / ROWS_PER_B;
        bidx[i] = b;
        #pragma unroll
        for (int j = 0; j < 8; j++)
            acc[i][j] += b1v[j] + g_vw3[b * Hn + tx * 8 + j];
    }

    float rowacc[8];
    #pragma unroll
    for (int i = 0; i < 8; i++) rowacc[i] = 0.f;

    for (int t = 0; t < Tn; t++) {
        float cj[8];
        #pragma unroll
        for (int j = 0; j < 8; j++) cj[j] = g_contrib[t * Hn + tx * 8 + j];
        #pragma unroll
        for (int i = 0; i < 8; i++) {
            float p = 0.f;
            #pragma unroll
            for (int j = 0; j < 8; j++)
                p = fmaf(fmaxf(acc[i][j] + cj[j], 0.f), wov[j], p);
            // reduce across 16 lanes sharing this row
            #pragma unroll
            for (int off = 8; off > 0; off >>= 1)
                p += __shfl_down_sync(0xffffffffu, p, off, 16);
            if (tx == 0) {
                float x = p + bo;
                float sig = 1.f / (1.f + __expf(-x));
                float sc = sig * g_probs[bidx[i] * Tn + t] - 0.01f;
                rowacc[i] += fmaxf(sc, 0.f);
            }
        }
    }

    if (tx == 0) {
        #pragma unroll
        for (int i = 0; i < 8; i++) {
            int row = m0 + ty * 8 + i;
            float v = rowacc[i] * (1.f / (float)Tn);
            out[row] = v;
            if (out_size >= 2 * Mrows) out[Mrows + row] = v;  // (overall, overall)
        }
    }
}

// ---------------------------------------------------------------------------
extern "C" void kernel_launch(void* const* d_in, const int* in_sizes, int n_in,
                              void* d_out, int out_size) {
    const float* batch     = (const float*)d_in[0];
    const int*   seg_len   = (const int*)  d_in[1];
    const float* concept1  = (const float*)d_in[2];
    const float* concept2  = (const float*)d_in[3];
    const float* W_enc     = (const float*)d_in[4];
    const float* b_enc     = (const float*)d_in[5];
    const float* Wc1       = (const float*)d_in[6];
    const float* Wc2       = (const float*)d_in[7];
    const float* Wt1       = (const float*)d_in[8];
    const float* bt1       = (const float*)d_in[9];
    const float* Wt2       = (const float*)d_in[10];
    const float* bt2       = (const float*)d_in[11];
    const float* topic_emb = (const float*)d_in[12];
    const float* W1        = (const float*)d_in[13];
    const float* b1        = (const float*)d_in[14];
    const float* W2        = (const float*)d_in[15];
    const float* W3        = (const float*)d_in[16];
    const float* w_out     = (const float*)d_in[17];
    const float* b_out     = (const float*)d_in[18];
    float* out = (float*)d_out;

    zero_pool_kernel<<<(Bsz * Dsz + 255) / 256, 256>>>();
    pool_kernel<<<dim3(Dsz / 256, Ssz, Bsz), 256>>>(batch, seg_len);
    contrib_kernel<<<Tn, Hn>>>(topic_emb, W2);
    small_kernel<<<Bsz, Hn>>>(seg_len, concept1, concept2, W_enc, b_enc,
                              Wc1, Wc2, Wt1, bt1, Wt2, bt2, W3);
    gemm_epilogue_kernel<<<Mrows / BM, 256>>>(batch, W1, b1, w_out, b_out,
                                              out, out_size);
}

// round 3
// speedup vs baseline: 2.4193x; 2.4193x over previous
#include <cuda_runtime.h>
#include <cuda_bf16.h>
#include <stdint.h>

// Problem constants
#define Bsz 8
#define Ssz 20
#define Fsz 200
#define Dsz 2048
#define Tn  20
#define En  128
#define Hn  128
#define CDn 300
#define THn 128
#define Mrows (Bsz*Ssz*Fsz)     // 32000
#define ROWS_PER_B (Ssz*Fsz)    // 4000

// Scratch (no allocations allowed)
__device__ float g_pool[Bsz*Dsz];                 // masked sum over (s,f) per (b,d)
__device__ float g_vw3[Bsz*Hn];                   // video @ W3
__device__ float g_probs[Bsz*Tn];                 // topic softmax probs
__device__ float g_contrib[Tn*Hn];                // topic_emb @ W2
__device__ __nv_bfloat16 g_Whi[Hn*Dsz];           // W1^T hi  [n][k]
__device__ __nv_bfloat16 g_Wlo[Hn*Dsz];           // W1^T lo  [n][k]

// ---------------------------------------------------------------------------
__global__ void zero_pool_kernel() {
    int i = blockIdx.x * 256 + threadIdx.x;
    if (i < Bsz * Dsz) g_pool[i] = 0.f;
}

// grid (D/256, S, B), 256 threads: sum valid frames into g_pool
__global__ void pool_kernel(const float* __restrict__ batch,
                            const int* __restrict__ seg_len) {
    int b = blockIdx.z, s = blockIdx.y;
    int d = blockIdx.x * 256 + threadIdx.x;
    int len = seg_len[b * Ssz + s];
    const float* p = batch + ((size_t)(b * Ssz + s)) * Fsz * Dsz + d;
    float acc = 0.f;
    #pragma unroll 4
    for (int f = 0; f < len; f++) acc += p[(size_t)f * Dsz];
    atomicAdd(&g_pool[b * Dsz + d], acc);
}

// split+transpose W1 [K=2048][N=128] -> g_Whi/g_Wlo [N][K] bf16
__global__ void wsplit_kernel(const float* __restrict__ W1) {
    int idx = blockIdx.x * 256 + threadIdx.x;      // 0..262143
    int n = idx >> 11;
    int k = idx & 2047;
    float v = W1[k * Hn + n];
    __nv_bfloat16 h = __float2bfloat16(v);
    g_Whi[n * Dsz + k] = h;
    g_Wlo[n * Dsz + k] = __float2bfloat16(v - __bfloat162float(h));
}

// grid Tn blocks, Hn threads
__global__ void contrib_kernel(const float* __restrict__ topic_emb,
                               const float* __restrict__ W2) {
    int t = blockIdx.x, h = threadIdx.x;
    float acc = 0.f;
    #pragma unroll 8
    for (int e = 0; e < En; e++) acc += topic_emb[t * En + e] * W2[e * Hn + h];
    g_contrib[t * Hn + h] = acc;
}

// grid Bsz blocks, 1024 threads: video, topic probs, vw3 (8-way K-split)
__global__ void small_kernel(const int* __restrict__ seg_len,
                             const float* __restrict__ concept1,
                             const float* __restrict__ concept2,
                             const float* __restrict__ W_enc,
                             const float* __restrict__ b_enc,
                             const float* __restrict__ Wc1,
                             const float* __restrict__ Wc2,
                             const float* __restrict__ Wt1,
                             const float* __restrict__ bt1,
                             const float* __restrict__ Wt2,
                             const float* __restrict__ bt2,
                             const float* __restrict__ W3) {
    int b = blockIdx.x;
    int tid = threadIdx.x;
    int h  = tid & 127;
    int sl = tid >> 7;                 // 0..7
    __shared__ float part[8][Hn];
    __shared__ float part2[8][Hn];
    __shared__ float video[Hn];
    __shared__ float th[THn];
    __shared__ float logits[Tn];

    int cnt = 0;
    for (int s = 0; s < Ssz; s++) cnt += seg_len[b * Ssz + s];
    float inv = 1.f / fmaxf((float)cnt, 1.f);

    // pooled @ W_enc  (d split into 8 slices of 256)
    float acc = 0.f;
    {
        int d0 = sl * 256;
        #pragma unroll 4
        for (int i = 0; i < 256; i++) {
            int d = d0 + i;
            acc += (g_pool[b * Dsz + d] * inv) * W_enc[d * Hn + h];
        }
    }
    // concepts (c split: 38 per slice, last slice 34)
    {
        int c0 = sl * 38;
        int c1 = min(c0 + 38, CDn);
        #pragma unroll 2
        for (int c = c0; c < c1; c++)
            acc += concept1[b * CDn + c] * Wc1[c * Hn + h]
                 + concept2[b * CDn + c] * Wc2[c * Hn + h];
    }
    part[sl][h] = acc;
    __syncthreads();
    if (sl == 0) {
        float a = b_enc[h];
        #pragma unroll
        for (int j = 0; j < 8; j++) a += part[j][h];
        video[h] = fmaxf(a, 0.f);
    }
    __syncthreads();

    // th = relu(video@Wt1 + bt1), vw3 = video@W3  (k split: 16 per slice)
    {
        float a2 = 0.f, a3 = 0.f;
        int k0 = sl * 16;
        #pragma unroll
        for (int i = 0; i < 16; i++) {
            int k = k0 + i;
            float v = video[k];
            a2 += v * Wt1[k * THn + h];
            a3 += v * W3[k * Hn + h];
        }
        part[sl][h] = a2;
        part2[sl][h] = a3;
    }
    __syncthreads();
    if (sl == 0) {
        float a2 = bt1[h], a3 = 0.f;
        #pragma unroll
        for (int j = 0; j < 8; j++) { a2 += part[j][h]; a3 += part2[j][h]; }
        th[h] = fmaxf(a2, 0.f);
        g_vw3[b * Hn + h] = a3;
    }
    __syncthreads();

    if (tid < Tn) {
        float a4 = bt2[tid];
        #pragma unroll 8
        for (int k = 0; k < THn; k++) a4 += th[k] * Wt2[k * Tn + tid];
        logits[tid] = a4;
    }
    __syncthreads();
    if (tid == 0) {
        float m = -1e30f;
        for (int t = 0; t < Tn; t++) m = fmaxf(m, logits[t]);
        float ssum = 0.f;
        for (int t = 0; t < Tn; t++) { float e = __expf(logits[t] - m); logits[t] = e; ssum += e; }
        float invs = 1.f / ssum;
        for (int t = 0; t < Tn; t++) g_probs[b * Tn + t] = logits[t] * invs;
    }
}

// ---------------------------------------------------------------------------
// Tensor-core GEMM (batch[32000,2048] @ W1[2048,128]) via bf16 hi/lo 3-MMA
// split, with fused topic-loop epilogue. BM=128, BN=128, BK=32, 256 threads.
#define BM 128
#define KCH 32
#define PADK 40                         // bf16 row stride (conflict-free frags)

__device__ __forceinline__ void mma16816(float* d, const uint32_t* a, const uint32_t* b) {
    asm volatile(
        "mma.sync.aligned.m16n8k16.row.col.f32.bf16.bf16.f32 "
        "{%0,%1,%2,%3}, {%4,%5,%6,%7}, {%8,%9}, {%0,%1,%2,%3};"
        : "+f"(d[0]), "+f"(d[1]), "+f"(d[2]), "+f"(d[3])
        : "r"(a[0]), "r"(a[1]), "r"(a[2]), "r"(a[3]), "r"(b[0]), "r"(b[1]));
}

__global__ __launch_bounds__(256, 1)
void gemm_tc_kernel(const float* __restrict__ batch,
                    const float* __restrict__ b1,
                    const float* __restrict__ w_out,
                    const float* __restrict__ b_out_p,
                    float* __restrict__ out,
                    int out_size) {
    __shared__ __nv_bfloat16 Ah[BM * PADK];        // 10240 B
    __shared__ __nv_bfloat16 Al[BM * PADK];
    __shared__ __nv_bfloat16 Bh[Hn * PADK];
    __shared__ __nv_bfloat16 Bl[Hn * PADK];
    __shared__ float s_vw3[Bsz * Hn];              // 4 KB
    __shared__ float s_red[2][64][4];              // 2 KB
    __shared__ float s_wout[Hn];
    __shared__ float s_b1[Hn];
    __shared__ float s_probs[Bsz * Tn];

    int tid = threadIdx.x;
    int m0 = blockIdx.x * BM;

    // preload small params
    for (int i = tid; i < Bsz * Hn; i += 256) s_vw3[i] = g_vw3[i];
    if (tid < Hn) { s_wout[tid] = w_out[tid]; s_b1[tid] = b1[tid]; }
    if (tid < Bsz * Tn) s_probs[tid] = g_probs[tid];

    int wid = tid >> 5, lane = tid & 31;
    int wm = wid >> 2, wn = wid & 3;               // warp tile: 64 rows x 32 cols
    int r = lane >> 2, q = lane & 3;

    float acc[4][4][4];
    #pragma unroll
    for (int mt = 0; mt < 4; mt++)
        #pragma unroll
        for (int nt = 0; nt < 4; nt++)
            #pragma unroll
            for (int e = 0; e < 4; e++) acc[mt][nt][e] = 0.f;

    // load mapping: row = tid>>1 (0..127), kb = (tid&1)*16
    int lrow = tid >> 1;
    int lkb  = (tid & 1) * 16;
    const float* aptr = batch + (size_t)(m0 + lrow) * Dsz + lkb;
    const __nv_bfloat16* bhptr = g_Whi + (size_t)lrow * Dsz + lkb;
    const __nv_bfloat16* blptr = g_Wlo + (size_t)lrow * Dsz + lkb;

    float4 ar[4];
    uint4 brh[2], brl[2];

    // prologue load (chunk 0)
    #pragma unroll
    for (int i = 0; i < 4; i++) ar[i] = *(const float4*)(aptr + i * 4);
    brh[0] = *(const uint4*)(bhptr);     brh[1] = *(const uint4*)(bhptr + 8);
    brl[0] = *(const uint4*)(blptr);     brl[1] = *(const uint4*)(blptr + 8);

    for (int kc = 0; kc < Dsz / KCH; kc++) {
        __syncthreads();   // previous compute done (also covers s_* preload)
        // STS current regs (split A to hi/lo)
        {
            __nv_bfloat16* ahp = Ah + lrow * PADK + lkb;
            __nv_bfloat16* alp = Al + lrow * PADK + lkb;
            #pragma unroll
            for (int i = 0; i < 4; i++) {
                float4 v = ar[i];
                __nv_bfloat16 h0 = __float2bfloat16(v.x);
                __nv_bfloat16 h1 = __float2bfloat16(v.y);
                __nv_bfloat16 h2 = __float2bfloat16(v.z);
                __nv_bfloat16 h3 = __float2bfloat16(v.w);
                __nv_bfloat16 l0 = __float2bfloat16(v.x - __bfloat162float(h0));
                __nv_bfloat16 l1 = __float2bfloat16(v.y - __bfloat162float(h1));
                __nv_bfloat16 l2 = __float2bfloat16(v.z - __bfloat162float(h2));
                __nv_bfloat16 l3 = __float2bfloat16(v.w - __bfloat162float(h3));
                *(__nv_bfloat162*)(ahp + i * 4)     = __nv_bfloat162(h0, h1);
                *(__nv_bfloat162*)(ahp + i * 4 + 2) = __nv_bfloat162(h2, h3);
                *(__nv_bfloat162*)(alp + i * 4)     = __nv_bfloat162(l0, l1);
                *(__nv_bfloat162*)(alp + i * 4 + 2) = __nv_bfloat162(l2, l3);
            }
            *(uint4*)(Bh + lrow * PADK + lkb)     = brh[0];
            *(uint4*)(Bh + lrow * PADK + lkb + 8) = brh[1];
            *(uint4*)(Bl + lrow * PADK + lkb)     = brl[0];
            *(uint4*)(Bl + lrow * PADK + lkb + 8) = brl[1];
        }
        __syncthreads();

        // prefetch next chunk
        if (kc < Dsz / KCH - 1) {
            int k0 = (kc + 1) * KCH;
            #pragma unroll
            for (int i = 0; i < 4; i++) ar[i] = *(const float4*)(aptr + k0 + i * 4);
            brh[0] = *(const uint4*)(bhptr + k0);     brh[1] = *(const uint4*)(bhptr + k0 + 8);
            brl[0] = *(const uint4*)(blptr + k0);     brl[1] = *(const uint4*)(blptr + k0 + 8);
        }

        // compute: 2 k-steps of 16
        #pragma unroll
        for (int ks = 0; ks < 2; ks++) {
            int kb = ks * 16;
            uint32_t afh[4][4], afl[4][4];
            #pragma unroll
            for (int mt = 0; mt < 4; mt++) {
                int row0 = wm * 64 + mt * 16 + r;
                const __nv_bfloat16* p = Ah + row0 * PADK + kb + 2 * q;
                const __nv_bfloat16* pl = Al + row0 * PADK + kb + 2 * q;
                afh[mt][0] = *(const uint32_t*)(p);
                afh[mt][1] = *(const uint32_t*)(p + 8 * PADK);
                afh[mt][2] = *(const uint32_t*)(p + 8);
                afh[mt][3] = *(const uint32_t*)(p + 8 * PADK + 8);
                afl[mt][0] = *(const uint32_t*)(pl);
                afl[mt][1] = *(const uint32_t*)(pl + 8 * PADK);
                afl[mt][2] = *(const uint32_t*)(pl + 8);
                afl[mt][3] = *(const uint32_t*)(pl + 8 * PADK + 8);
            }
            uint32_t bfh[4][2], bfl[4][2];
            #pragma unroll
            for (int nt = 0; nt < 4; nt++) {
                int n = wn * 32 + nt * 8 + r;
                const __nv_bfloat16* p = Bh + n * PADK + kb + 2 * q;
                const __nv_bfloat16* pl = Bl + n * PADK + kb + 2 * q;
                bfh[nt][0] = *(const uint32_t*)(p);
                bfh[nt][1] = *(const uint32_t*)(p + 8);
                bfl[nt][0] = *(const uint32_t*)(pl);
                bfl[nt][1] = *(const uint32_t*)(pl + 8);
            }
            #pragma unroll
            for (int mt = 0; mt < 4; mt++)
                #pragma unroll
                for (int nt = 0; nt < 4; nt++) {
                    mma16816(acc[mt][nt], afh[mt], bfh[nt]);
                    mma16816(acc[mt][nt], afh[mt], bfl[nt]);
                    mma16816(acc[mt][nt], afl[mt], bfh[nt]);
                }
        }
    }

    // ----- Epilogue: base = acc + b1 + vw3[b]; 20-topic relu/score loop -----
    float bo = b_out_p[0];
    #pragma unroll
    for (int mt = 0; mt < 4; mt++) {
        int rg0 = m0 + wm * 64 + mt * 16 + r;
        int rg1 = rg0 + 8;
        int b0 = rg0 / ROWS_PER_B;
        int b1i = rg1 / ROWS_PER_B;
        #pragma unroll
        for (int nt = 0; nt < 4; nt++)
            #pragma unroll
            for (int e = 0; e < 2; e++) {
                int col = wn * 32 + nt * 8 + 2 * q + e;
                acc[mt][nt][e]     += s_b1[col] + s_vw3[b0 * Hn + col];
                acc[mt][nt][2 + e] += s_b1[col] + s_vw3[b1i * Hn + col];
            }
    }

    float orow = 0.f;     // per-row accumulator for threads tid<128
    int myrow = m0 + tid;
    int myb = (tid < 128) ? (myrow / ROWS_PER_B) : 0;

    for (int t = 0; t < Tn; t++) {
        float cv[4][2], wv[4][2];
        #pragma unroll
        for (int nt = 0; nt < 4; nt++)
            #pragma unroll
            for (int e = 0; e < 2; e++) {
                int col = wn * 32 + nt * 8 + 2 * q + e;
                cv[nt][e] = __ldg(&g_contrib[t * Hn + col]);
                wv[nt][e] = s_wout[col];
            }
        #pragma unroll
        for (int mt = 0; mt < 4; mt++) {
            float p0 = 0.f, p1 = 0.f;
            #pragma unroll
            for (int nt = 0; nt < 4; nt++)
                #pragma unroll
                for (int e = 0; e < 2; e++) {
                    p0 = fmaf(fmaxf(acc[mt][nt][e]     + cv[nt][e], 0.f), wv[nt][e], p0);
                    p1 = fmaf(fmaxf(acc[mt][nt][2 + e] + cv[nt][e], 0.f), wv[nt][e], p1);
                }
            p0 += __shfl_xor_sync(0xffffffffu, p0, 1);
            p0 += __shfl_xor_sync(0xffffffffu, p0, 2);
            p1 += __shfl_xor_sync(0xffffffffu, p1, 1);
            p1 += __shfl_xor_sync(0xffffffffu, p1, 2);
            if (q == 0) {
                s_red[wm][mt * 16 + r][wn]     = p0;
                s_red[wm][mt * 16 + r + 8][wn] = p1;
            }
        }
        __syncthreads();
        if (tid < 128) {
            float s = s_red[tid >> 6][tid & 63][0] + s_red[tid >> 6][tid & 63][1]
                    + s_red[tid >> 6][tid & 63][2] + s_red[tid >> 6][tid & 63][3] + bo;
            float sig = 1.f / (1.f + __expf(-s));
            float sc = sig * s_probs[myb * Tn + t] - 0.01f;
            orow += fmaxf(sc, 0.f);
        }
        __syncthreads();
    }

    if (tid < 128) {
        float v = orow * (1.f / (float)Tn);
        out[myrow] = v;
        if (out_size >= 2 * Mrows) out[Mrows + myrow] = v;
    }
}

// ---------------------------------------------------------------------------
extern "C" void kernel_launch(void* const* d_in, const int* in_sizes, int n_in,
                              void* d_out, int out_size) {
    const float* batch     = (const float*)d_in[0];
    const int*   seg_len   = (const int*)  d_in[1];
    const float* concept1  = (const float*)d_in[2];
    const float* concept2  = (const float*)d_in[3];
    const float* W_enc     = (const float*)d_in[4];
    const float* b_enc     = (const float*)d_in[5];
    const float* Wc1       = (const float*)d_in[6];
    const float* Wc2       = (const float*)d_in[7];
    const float* Wt1       = (const float*)d_in[8];
    const float* bt1       = (const float*)d_in[9];
    const float* Wt2       = (const float*)d_in[10];
    const float* bt2       = (const float*)d_in[11];
    const float* topic_emb = (const float*)d_in[12];
    const float* W1        = (const float*)d_in[13];
    const float* b1        = (const float*)d_in[14];
    const float* W2        = (const float*)d_in[15];
    const float* W3        = (const float*)d_in[16];
    const float* w_out     = (const float*)d_in[17];
    const float* b_out     = (const float*)d_in[18];
    float* out = (float*)d_out;

    zero_pool_kernel<<<(Bsz * Dsz + 255) / 256, 256>>>();
    pool_kernel<<<dim3(Dsz / 256, Ssz, Bsz), 256>>>(batch, seg_len);
    wsplit_kernel<<<(Hn * Dsz) / 256, 256>>>(W1);
    contrib_kernel<<<Tn, Hn>>>(topic_emb, W2);
    small_kernel<<<Bsz, 1024>>>(seg_len, concept1, concept2, W_enc, b_enc,
                                Wc1, Wc2, Wt1, bt1, Wt2, bt2, W3);
    gemm_tc_kernel<<<Mrows / BM, 256>>>(batch, b1, w_out, b_out, out, out_size);
}

// round 5
// speedup vs baseline: 2.7585x; 1.1402x over previous
#include <cuda_runtime.h>
#include <cuda_bf16.h>
#include <stdint.h>

// Problem constants
#define Bsz 8
#define Ssz 20
#define Fsz 200
#define Dsz 2048
#define Tn  20
#define En  128
#define Hn  128
#define CDn 300
#define THn 128
#define Mrows (Bsz*Ssz*Fsz)     // 32000
#define ROWS_PER_B (Ssz*Fsz)    // 4000

// Scratch (no allocations allowed)
__device__ float g_pool[Bsz*Dsz];
__device__ float g_vw3[Bsz*Hn];
__device__ float g_probs[Bsz*Tn];
__device__ float g_contrib[Tn*Hn];
__device__ __nv_bfloat16 g_Whi[Hn*Dsz];           // W1^T hi  [n][k]
__device__ __nv_bfloat16 g_Wlo[Hn*Dsz];           // W1^T lo  [n][k]

// ---------------------------------------------------------------------------
// PTX helpers (legacy tensor path only — toolchain targets sm_100 w/o 'a')
// ---------------------------------------------------------------------------
__device__ __forceinline__ uint32_t smem_u32(const void* p) {
    uint32_t a;
    asm("{ .reg .u64 t; cvta.to.shared.u64 t, %1; cvt.u32.u64 %0, t; }"
        : "=r"(a) : "l"(p));
    return a;
}
__device__ __forceinline__ void mma16816(float* d, const uint32_t* a, const uint32_t* b) {
    asm volatile(
        "mma.sync.aligned.m16n8k16.row.col.f32.bf16.bf16.f32 "
        "{%0,%1,%2,%3}, {%4,%5,%6,%7}, {%8,%9}, {%0,%1,%2,%3};"
        : "+f"(d[0]), "+f"(d[1]), "+f"(d[2]), "+f"(d[3])
        : "r"(a[0]), "r"(a[1]), "r"(a[2]), "r"(a[3]), "r"(b[0]), "r"(b[1]));
}
#define LDSM4(r0, r1, r2, r3, addr) \
    asm volatile("ldmatrix.sync.aligned.m8n8.x4.shared.b16 {%0,%1,%2,%3}, [%4];" \
                 : "=r"(r0), "=r"(r1), "=r"(r2), "=r"(r3) : "r"(addr))
#define CP_ASYNC16(dst, src) \
    asm volatile("cp.async.cg.shared.global [%0], [%1], 16;" :: "r"(dst), "l"(src))
#define CP_COMMIT() asm volatile("cp.async.commit_group;")
#define CP_WAIT1()  asm volatile("cp.async.wait_group 1;")
#define CP_WAIT0()  asm volatile("cp.async.wait_group 0;")
#define CVTPACK(d, lo, hi) \
    asm("cvt.rn.bf16x2.f32 %0, %1, %2;" : "=r"(d) : "f"(hi), "f"(lo))

// ---------------------------------------------------------------------------
// prep: contrib + zero g_pool + split/transpose W1.  grid (Tn+64+1024) x 256
// ---------------------------------------------------------------------------
__global__ void prep_kernel(const float* __restrict__ W1,
                            const float* __restrict__ topic_emb,
                            const float* __restrict__ W2) {
    int bx = blockIdx.x, tid = threadIdx.x;
    if (bx < Tn) {
        __shared__ float red[2][Hn];
        int h = tid & 127, e2 = tid >> 7;
        float acc = 0.f;
        int e0 = e2 * 64;
        #pragma unroll 8
        for (int e = e0; e < e0 + 64; e++)
            acc += topic_emb[bx * En + e] * W2[e * Hn + h];
        red[e2][h] = acc;
        __syncthreads();
        if (e2 == 0) g_contrib[bx * Hn + h] = red[0][h] + red[1][h];
    } else if (bx < Tn + 64) {
        g_pool[(bx - Tn) * 256 + tid] = 0.f;
    } else {
        int idx = (bx - Tn - 64) * 256 + tid;       // 0..262143
        int n = idx >> 11, k = idx & 2047;
        float v = W1[k * Hn + n];
        __nv_bfloat16 h = __float2bfloat16(v);
        g_Whi[n * Dsz + k] = h;
        g_Wlo[n * Dsz + k] = __float2bfloat16(v - __bfloat162float(h));
    }
}

// grid (8, 20, 8), 256 threads
__global__ void pool_kernel(const float* __restrict__ batch,
                            const int* __restrict__ seg_len) {
    int b = blockIdx.z, s = blockIdx.y;
    int d = blockIdx.x * 256 + threadIdx.x;
    int len = seg_len[b * Ssz + s];
    const float* p = batch + ((size_t)(b * Ssz + s)) * Fsz * Dsz + d;
    float acc = 0.f;
    #pragma unroll 4
    for (int f = 0; f < len; f++) acc += p[(size_t)f * Dsz];
    atomicAdd(&g_pool[b * Dsz + d], acc);
}

// grid Bsz blocks, 1024 threads
__global__ void small_kernel(const int* __restrict__ seg_len,
                             const float* __restrict__ concept1,
                             const float* __restrict__ concept2,
                             const float* __restrict__ W_enc,
                             const float* __restrict__ b_enc,
                             const float* __restrict__ Wc1,
                             const float* __restrict__ Wc2,
                             const float* __restrict__ Wt1,
                             const float* __restrict__ bt1,
                             const float* __restrict__ Wt2,
                             const float* __restrict__ bt2,
                             const float* __restrict__ W3) {
    int b = blockIdx.x;
    int tid = threadIdx.x;
    int h  = tid & 127;
    int sl = tid >> 7;
    __shared__ float part[8][Hn];
    __shared__ float part2[8][Hn];
    __shared__ float video[Hn];
    __shared__ float th[THn];
    __shared__ float logits[Tn];

    int cnt = 0;
    for (int s = 0; s < Ssz; s++) cnt += seg_len[b * Ssz + s];
    float inv = 1.f / fmaxf((float)cnt, 1.f);

    float acc = 0.f;
    {
        int d0 = sl * 256;
        #pragma unroll 4
        for (int i = 0; i < 256; i++) {
            int d = d0 + i;
            acc += (g_pool[b * Dsz + d] * inv) * W_enc[d * Hn + h];
        }
    }
    {
        int c0 = sl * 38;
        int c1 = min(c0 + 38, CDn);
        #pragma unroll 2
        for (int c = c0; c < c1; c++)
            acc += concept1[b * CDn + c] * Wc1[c * Hn + h]
                 + concept2[b * CDn + c] * Wc2[c * Hn + h];
    }
    part[sl][h] = acc;
    __syncthreads();
    if (sl == 0) {
        float a = b_enc[h];
        #pragma unroll
        for (int j = 0; j < 8; j++) a += part[j][h];
        video[h] = fmaxf(a, 0.f);
    }
    __syncthreads();
    {
        float a2 = 0.f, a3 = 0.f;
        int k0 = sl * 16;
        #pragma unroll
        for (int i = 0; i < 16; i++) {
            int k = k0 + i;
            float v = video[k];
            a2 += v * Wt1[k * THn + h];
            a3 += v * W3[k * Hn + h];
        }
        part[sl][h] = a2;
        part2[sl][h] = a3;
    }
    __syncthreads();
    if (sl == 0) {
        float a2 = bt1[h], a3 = 0.f;
        #pragma unroll
        for (int j = 0; j < 8; j++) { a2 += part[j][h]; a3 += part2[j][h]; }
        th[h] = fmaxf(a2, 0.f);
        g_vw3[b * Hn + h] = a3;
    }
    __syncthreads();
    if (tid < Tn) {
        float a4 = bt2[tid];
        #pragma unroll 8
        for (int k = 0; k < THn; k++) a4 += th[k] * Wt2[k * Tn + tid];
        logits[tid] = a4;
    }
    __syncthreads();
    if (tid == 0) {
        float m = -1e30f;
        for (int t = 0; t < Tn; t++) m = fmaxf(m, logits[t]);
        float ssum = 0.f;
        for (int t = 0; t < Tn; t++) { float e = __expf(logits[t] - m); logits[t] = e; ssum += e; }
        float invs = 1.f / ssum;
        for (int t = 0; t < Tn; t++) g_probs[b * Tn + t] = logits[t] * invs;
    }
}

// ---------------------------------------------------------------------------
// bf16 hi/lo 3-term GEMM (batch @ W1) + fused topic epilogue.
// BM=128, BN=128, KCH=64 (SW128 rows), double-buffered, ldmatrix + cp.async.
// ---------------------------------------------------------------------------
#define KCH   64
#define NCHK  (Dsz / KCH)               // 32
#define BUF_STRIDE 65536                // Ah 16K | Al 16K | Bh 16K | Bl 16K
#define OFF_AL 16384
#define OFF_BH 32768
#define OFF_BL 49152
#define SM_CONTRIB 131072               // 10240 B
#define SM_VW3     141312               // 4096 B
#define SM_B1      145408               // 512 B
#define SM_WOUT    145920               // 512 B
#define SM_PROBS   146432               // 768 B (640 used)
#define SM_RED     147200               // 2048 B
#define SM_BYTES   (149248 + 1024)

__global__ __launch_bounds__(256, 1)
void gemm_tc_kernel(const float* __restrict__ batch,
                    const float* __restrict__ b1,
                    const float* __restrict__ w_out,
                    const float* __restrict__ b_out_p,
                    float* __restrict__ out,
                    int out_size) {
    extern __shared__ char smem_raw[];
    uint32_t sb0 = smem_u32(smem_raw);
    uint32_t sb = (sb0 + 1023) & ~1023u;
    char* smem = smem_raw + (sb - sb0);

    int tid = threadIdx.x;
    int wid = tid >> 5, lane = tid & 31;
    int m0 = blockIdx.x * 128;

    // epilogue-constant preload (covered by first in-loop __syncthreads)
    for (int i = tid; i < Tn * Hn; i += 256)
        ((float*)(smem + SM_CONTRIB))[i] = g_contrib[i];
    for (int i = tid; i < Bsz * Hn; i += 256)
        ((float*)(smem + SM_VW3))[i] = g_vw3[i];
    if (tid < Hn) {
        ((float*)(smem + SM_B1))[tid] = b1[tid];
        ((float*)(smem + SM_WOUT))[tid] = w_out[tid];
    }
    if (tid < Bsz * Tn)
        ((float*)(smem + SM_PROBS))[tid] = g_probs[tid];

    // ---- per-thread global-load mapping ----
    // A: row = tid>>1, half = tid&1 -> 32 fp32 (128 B)
    int lrow = tid >> 1;
    int half = tid & 1;
    const float* aptr = batch + (size_t)(m0 + lrow) * Dsz + half * 32;
    uint32_t a_sts[4];
    #pragma unroll
    for (int g = 0; g < 4; g++)
        a_sts[g] = (uint32_t)lrow * 128 +
                   (((uint32_t)(half * 64 + g * 16)) ^ (((uint32_t)lrow & 7) << 4));
    // B cp.async: 4 x 16B hi + 4 x 16B lo per thread per chunk
    int brow_g[4], bc16[4];
    uint32_t b_dst[4];
    #pragma unroll
    for (int j = 0; j < 4; j++) {
        int gid = tid + j * 256;
        brow_g[j] = gid >> 3;
        bc16[j] = gid & 7;
        b_dst[j] = (uint32_t)brow_g[j] * 128 +
                   (((uint32_t)(bc16[j] * 16)) ^ (((uint32_t)brow_g[j] & 7) << 4));
    }

    // ---- per-warp fragment mapping (ldmatrix) ----
    int wm = wid >> 2, wn = wid & 3;               // warp tile: 64 rows x 32 cols
    int lr = lane & 7, s1 = (lane >> 3) & 1, s2 = lane >> 4;
    uint32_t a_base[4], a_xor[4];
    #pragma unroll
    for (int mt = 0; mt < 4; mt++) {
        int arow = wm * 64 + mt * 16 + s1 * 8 + lr;
        a_base[mt] = (uint32_t)arow * 128;
        a_xor[mt] = ((uint32_t)arow & 7) << 4;
    }
    uint32_t b_base[2], b_xor[2];
    #pragma unroll
    for (int np = 0; np < 2; np++) {
        int brow = wn * 32 + np * 16 + s2 * 8 + lr;
        b_base[np] = (uint32_t)brow * 128;
        b_xor[np] = ((uint32_t)brow & 7) << 4;
    }
    uint32_t a_kadd = (uint32_t)(s2 * 16);
    uint32_t b_kadd = (uint32_t)(s1 * 16);

    float acc[4][4][4];
    #pragma unroll
    for (int mt = 0; mt < 4; mt++)
        #pragma unroll
        for (int nt = 0; nt < 4; nt++)
            #pragma unroll
            for (int e = 0; e < 4; e++) acc[mt][nt][e] = 0.f;

    // ---- prologue: LDG A chunk0 ; cp.async B chunk0->buf0, chunk1->buf1 ----
    float4 ar[8];
    #pragma unroll
    for (int g = 0; g < 8; g++) ar[g] = ((const float4*)aptr)[g];
    #pragma unroll
    for (int c = 0; c < 2; c++) {
        uint32_t bB = sb + c * BUF_STRIDE;
        int k0 = c * KCH;
        #pragma unroll
        for (int j = 0; j < 4; j++) {
            const __nv_bfloat16* sh = g_Whi + (size_t)brow_g[j] * Dsz + k0 + bc16[j] * 8;
            const __nv_bfloat16* slp = g_Wlo + (size_t)brow_g[j] * Dsz + k0 + bc16[j] * 8;
            CP_ASYNC16(bB + OFF_BH + b_dst[j], sh);
            CP_ASYNC16(bB + OFF_BL + b_dst[j], slp);
        }
        CP_COMMIT();
    }

    for (int c = 0; c < NCHK; c++) {
        int p = c & 1;
        if (c == NCHK - 1) { CP_WAIT0(); } else { CP_WAIT1(); }

        // STS A (convert fp32 -> bf16 hi/lo)
        {
            char* bah = smem + p * BUF_STRIDE;
            char* bal = bah + OFF_AL;
            #pragma unroll
            for (int g = 0; g < 4; g++) {
                float4 v0 = ar[2 * g], v1 = ar[2 * g + 1];
                uint32_t h01, h23, h45, h67;
                CVTPACK(h01, v0.x, v0.y);
                CVTPACK(h23, v0.z, v0.w);
                CVTPACK(h45, v1.x, v1.y);
                CVTPACK(h67, v1.z, v1.w);
                float r0 = v0.x - __uint_as_float(h01 << 16);
                float r1 = v0.y - __uint_as_float(h01 & 0xffff0000u);
                float r2 = v0.z - __uint_as_float(h23 << 16);
                float r3 = v0.w - __uint_as_float(h23 & 0xffff0000u);
                float r4 = v1.x - __uint_as_float(h45 << 16);
                float r5 = v1.y - __uint_as_float(h45 & 0xffff0000u);
                float r6 = v1.z - __uint_as_float(h67 << 16);
                float r7 = v1.w - __uint_as_float(h67 & 0xffff0000u);
                uint32_t l01, l23, l45, l67;
                CVTPACK(l01, r0, r1);
                CVTPACK(l23, r2, r3);
                CVTPACK(l45, r4, r5);
                CVTPACK(l67, r6, r7);
                *(uint4*)(bah + a_sts[g]) = make_uint4(h01, h23, h45, h67);
                *(uint4*)(bal + a_sts[g]) = make_uint4(l01, l23, l45, l67);
            }
        }
        __syncthreads();

        // prefetch next A chunk into regs
        if (c + 1 < NCHK) {
            const float4* ap = (const float4*)(aptr + (c + 1) * KCH);
            #pragma unroll
            for (int g = 0; g < 8; g++) ar[g] = ap[g];
        }

        // compute on buffer p: 4 k16 steps
        {
            uint32_t Ahb = sb + p * BUF_STRIDE;
            uint32_t Alb = Ahb + OFF_AL;
            uint32_t Bhb = Ahb + OFF_BH;
            uint32_t Blb = Ahb + OFF_BL;
            #pragma unroll
            for (int ks = 0; ks < 4; ks++) {
                uint32_t ka = (uint32_t)(ks * 32) + a_kadd;
                uint32_t kb = (uint32_t)(ks * 32) + b_kadd;
                uint32_t afh[4][4], afl[4][4];
                #pragma unroll
                for (int mt = 0; mt < 4; mt++) {
                    LDSM4(afh[mt][0], afh[mt][1], afh[mt][2], afh[mt][3],
                          Ahb + a_base[mt] + (ka ^ a_xor[mt]));
                    LDSM4(afl[mt][0], afl[mt][1], afl[mt][2], afl[mt][3],
                          Alb + a_base[mt] + (ka ^ a_xor[mt]));
                }
                uint32_t bfh[4][2], bfl[4][2];
                #pragma unroll
                for (int np = 0; np < 2; np++) {
                    LDSM4(bfh[2 * np][0], bfh[2 * np][1], bfh[2 * np + 1][0], bfh[2 * np + 1][1],
                          Bhb + b_base[np] + (kb ^ b_xor[np]));
                    LDSM4(bfl[2 * np][0], bfl[2 * np][1], bfl[2 * np + 1][0], bfl[2 * np + 1][1],
                          Blb + b_base[np] + (kb ^ b_xor[np]));
                }
                #pragma unroll
                for (int mt = 0; mt < 4; mt++)
                    #pragma unroll
                    for (int nt = 0; nt < 4; nt++) {
                        mma16816(acc[mt][nt], afh[mt], bfh[nt]);
                        mma16816(acc[mt][nt], afh[mt], bfl[nt]);
                        mma16816(acc[mt][nt], afl[mt], bfh[nt]);
                    }
            }
        }
        __syncthreads();

        // issue B cp.async for chunk c+2 into buffer p (now free)
        if (c + 2 < NCHK) {
            uint32_t bB = sb + p * BUF_STRIDE;
            int k0 = (c + 2) * KCH;
            #pragma unroll
            for (int j = 0; j < 4; j++) {
                const __nv_bfloat16* sh = g_Whi + (size_t)brow_g[j] * Dsz + k0 + bc16[j] * 8;
                const __nv_bfloat16* slp = g_Wlo + (size_t)brow_g[j] * Dsz + k0 + bc16[j] * 8;
                CP_ASYNC16(bB + OFF_BH + b_dst[j], sh);
                CP_ASYNC16(bB + OFF_BL + b_dst[j], slp);
            }
            CP_COMMIT();
        }
    }

    // ----- Epilogue: base = acc + b1 + vw3[b]; 20-topic relu/score loop -----
    float* s_red   = (float*)(smem + SM_RED);          // [2][64][4]
    const float* s_vw3  = (const float*)(smem + SM_VW3);
    const float* s_b1v  = (const float*)(smem + SM_B1);
    const float* s_wo   = (const float*)(smem + SM_WOUT);
    const float* s_prob = (const float*)(smem + SM_PROBS);
    const float* s_con  = (const float*)(smem + SM_CONTRIB);
    float bo = b_out_p[0];
    int r = lane >> 2, q = lane & 3;

    #pragma unroll
    for (int mt = 0; mt < 4; mt++) {
        int rg0 = m0 + wm * 64 + mt * 16 + r;
        int rg1 = rg0 + 8;
        int b0 = rg0 / ROWS_PER_B;
        int b1i = rg1 / ROWS_PER_B;
        #pragma unroll
        for (int nt = 0; nt < 4; nt++)
            #pragma unroll
            for (int e = 0; e < 2; e++) {
                int col = wn * 32 + nt * 8 + 2 * q + e;
                acc[mt][nt][e]     += s_b1v[col] + s_vw3[b0 * Hn + col];
                acc[mt][nt][2 + e] += s_b1v[col] + s_vw3[b1i * Hn + col];
            }
    }

    float orow = 0.f;     // per-row accumulator for threads tid<128
    int myrow = m0 + tid;
    int myb = (tid < 128) ? (myrow / ROWS_PER_B) : 0;

    for (int t = 0; t < Tn; t++) {
        float cv[4][2], wv[4][2];
        #pragma unroll
        for (int nt = 0; nt < 4; nt++)
            #pragma unroll
            for (int e = 0; e < 2; e++) {
                int col = wn * 32 + nt * 8 + 2 * q + e;
                cv[nt][e] = s_con[t * Hn + col];
                wv[nt][e] = s_wo[col];
            }
        #pragma unroll
        for (int mt = 0; mt < 4; mt++) {
            float p0 = 0.f, p1 = 0.f;
            #pragma unroll
            for (int nt = 0; nt < 4; nt++)
                #pragma unroll
                for (int e = 0; e < 2; e++) {
                    p0 = fmaf(fmaxf(acc[mt][nt][e]     + cv[nt][e], 0.f), wv[nt][e], p0);
                    p1 = fmaf(fmaxf(acc[mt][nt][2 + e] + cv[nt][e], 0.f), wv[nt][e], p1);
                }
            p0 += __shfl_xor_sync(0xffffffffu, p0, 1);
            p0 += __shfl_xor_sync(0xffffffffu, p0, 2);
            p1 += __shfl_xor_sync(0xffffffffu, p1, 1);
            p1 += __shfl_xor_sync(0xffffffffu, p1, 2);
            if (q == 0) {
                s_red[(wm * 64 + mt * 16 + r) * 4 + wn]     = p0;
                s_red[(wm * 64 + mt * 16 + r + 8) * 4 + wn] = p1;
            }
        }
        __syncthreads();
        if (tid < 128) {
            float s = s_red[tid * 4 + 0] + s_red[tid * 4 + 1]
                    + s_red[tid * 4 + 2] + s_red[tid * 4 + 3] + bo;
            float sig = 1.f / (1.f + __expf(-s));
            float sc = sig * s_prob[myb * Tn + t] - 0.01f;
            orow += fmaxf(sc, 0.f);
        }
        __syncthreads();
    }

    if (tid < 128) {
        float v = orow * (1.f / (float)Tn);
        out[myrow] = v;
        if (out_size >= 2 * Mrows) out[Mrows + myrow] = v;
    }
}

// ---------------------------------------------------------------------------
extern "C" void kernel_launch(void* const* d_in, const int* in_sizes, int n_in,
                              void* d_out, int out_size) {
    const float* batch     = (const float*)d_in[0];
    const int*   seg_len   = (const int*)  d_in[1];
    const float* concept1  = (const float*)d_in[2];
    const float* concept2  = (const float*)d_in[3];
    const float* W_enc     = (const float*)d_in[4];
    const float* b_enc     = (const float*)d_in[5];
    const float* Wc1       = (const float*)d_in[6];
    const float* Wc2       = (const float*)d_in[7];
    const float* Wt1       = (const float*)d_in[8];
    const float* bt1       = (const float*)d_in[9];
    const float* Wt2       = (const float*)d_in[10];
    const float* bt2       = (const float*)d_in[11];
    const float* topic_emb = (const float*)d_in[12];
    const float* W1        = (const float*)d_in[13];
    const float* b1        = (const float*)d_in[14];
    const float* W2        = (const float*)d_in[15];
    const float* W3        = (const float*)d_in[16];
    const float* w_out     = (const float*)d_in[17];
    const float* b_out     = (const float*)d_in[18];
    float* out = (float*)d_out;

    cudaFuncSetAttribute(gemm_tc_kernel,
                         cudaFuncAttributeMaxDynamicSharedMemorySize, SM_BYTES);

    prep_kernel<<<Tn + 64 + (Hn * Dsz) / 256, 256>>>(W1, topic_emb, W2);
    pool_kernel<<<dim3(Dsz / 256, Ssz, Bsz), 256>>>(batch, seg_len);
    small_kernel<<<Bsz, 1024>>>(seg_len, concept1, concept2, W_enc, b_enc,
                                Wc1, Wc2, Wt1, bt1, Wt2, bt2, W3);
    gemm_tc_kernel<<<Mrows / 128, 256, SM_BYTES>>>(batch, b1, w_out, b_out,
                                                   out, out_size);
}

// round 6
// speedup vs baseline: 3.3269x; 1.2061x over previous
#include <cuda_runtime.h>
#include <cuda_fp16.h>
#include <stdint.h>

// Problem constants
#define Bsz 8
#define Ssz 20
#define Fsz 200
#define Dsz 2048
#define Tn  20
#define En  128
#define Hn  128
#define CDn 300
#define THn 128
#define Mrows (Bsz*Ssz*Fsz)     // 32000
#define ROWS_PER_B (Ssz*Fsz)    // 4000

// Scratch (no allocations allowed)
__device__ float g_pool[Bsz*Dsz];
__device__ float g_vw3[Bsz*Hn];
__device__ float g_probs[Bsz*Tn];
__device__ float g_contrib[Tn*Hn];
__device__ __half g_Wh[Hn*Dsz];                   // W1^T fp16  [n][k]

// ---------------------------------------------------------------------------
__device__ __forceinline__ uint32_t smem_u32(const void* p) {
    uint32_t a;
    asm("{ .reg .u64 t; cvta.to.shared.u64 t, %1; cvt.u32.u64 %0, t; }"
        : "=r"(a) : "l"(p));
    return a;
}
__device__ __forceinline__ void mma16816h(float* d, const uint32_t* a, const uint32_t* b) {
    asm volatile(
        "mma.sync.aligned.m16n8k16.row.col.f32.f16.f16.f32 "
        "{%0,%1,%2,%3}, {%4,%5,%6,%7}, {%8,%9}, {%0,%1,%2,%3};"
        : "+f"(d[0]), "+f"(d[1]), "+f"(d[2]), "+f"(d[3])
        : "r"(a[0]), "r"(a[1]), "r"(a[2]), "r"(a[3]), "r"(b[0]), "r"(b[1]));
}
#define LDSM4(r0, r1, r2, r3, addr) \
    asm volatile("ldmatrix.sync.aligned.m8n8.x4.shared.b16 {%0,%1,%2,%3}, [%4];" \
                 : "=r"(r0), "=r"(r1), "=r"(r2), "=r"(r3) : "r"(addr))
#define CP_ASYNC16(dst, src) \
    asm volatile("cp.async.cg.shared.global [%0], [%1], 16;" :: "r"(dst), "l"(src))
#define CP_COMMIT() asm volatile("cp.async.commit_group;")
#define CP_WAIT1()  asm volatile("cp.async.wait_group 1;")
#define CP_WAIT0()  asm volatile("cp.async.wait_group 0;")

__device__ __forceinline__ uint32_t packh2(__half a, __half b) {
    __half2 h = __halves2half2(a, b);
    return *(uint32_t*)&h;
}

// ---------------------------------------------------------------------------
// prep: contrib + zero g_pool + fp16 transpose of W1.  grid 1108 x 256
// ---------------------------------------------------------------------------
__global__ void prep_kernel(const float* __restrict__ W1,
                            const float* __restrict__ topic_emb,
                            const float* __restrict__ W2) {
    int bx = blockIdx.x, tid = threadIdx.x;
    if (bx < Tn) {
        __shared__ float red[2][Hn];
        int h = tid & 127, e2 = tid >> 7;
        float acc = 0.f;
        int e0 = e2 * 64;
        #pragma unroll 8
        for (int e = e0; e < e0 + 64; e++)
            acc += topic_emb[bx * En + e] * W2[e * Hn + h];
        red[e2][h] = acc;
        __syncthreads();
        if (e2 == 0) g_contrib[bx * Hn + h] = red[0][h] + red[1][h];
    } else if (bx < Tn + 64) {
        g_pool[(bx - Tn) * 256 + tid] = 0.f;
    } else {
        int idx = (bx - Tn - 64) * 256 + tid;       // 0..262143
        int n = idx >> 11, k = idx & 2047;
        g_Wh[n * Dsz + k] = __float2half_rn(W1[k * Hn + n]);
    }
}

// grid (8, 20, 32): z = b*4 + f-quarter, 256 threads
__global__ void pool_kernel(const float* __restrict__ batch,
                            const int* __restrict__ seg_len) {
    int b = blockIdx.z >> 2, fq = blockIdx.z & 3, s = blockIdx.y;
    int d = blockIdx.x * 256 + threadIdx.x;
    int len = seg_len[b * Ssz + s];
    int f0 = fq * 50;
    int f1 = min(len, f0 + 50);
    if (f0 >= f1) return;
    const float* p = batch + ((size_t)(b * Ssz + s)) * Fsz * Dsz + d;
    float acc = 0.f;
    #pragma unroll 5
    for (int f = f0; f < f1; f++) acc += p[(size_t)f * Dsz];
    atomicAdd(&g_pool[b * Dsz + d], acc);
}

// grid Bsz blocks, 1024 threads
__global__ void small_kernel(const int* __restrict__ seg_len,
                             const float* __restrict__ concept1,
                             const float* __restrict__ concept2,
                             const float* __restrict__ W_enc,
                             const float* __restrict__ b_enc,
                             const float* __restrict__ Wc1,
                             const float* __restrict__ Wc2,
                             const float* __restrict__ Wt1,
                             const float* __restrict__ bt1,
                             const float* __restrict__ Wt2,
                             const float* __restrict__ bt2,
                             const float* __restrict__ W3) {
    int b = blockIdx.x;
    int tid = threadIdx.x;
    int h  = tid & 127;
    int sl = tid >> 7;
    __shared__ float part[8][Hn];
    __shared__ float part2[8][Hn];
    __shared__ float video[Hn];
    __shared__ float th[THn];
    __shared__ float logits[Tn];

    int cnt = 0;
    for (int s = 0; s < Ssz; s++) cnt += seg_len[b * Ssz + s];
    float inv = 1.f / fmaxf((float)cnt, 1.f);

    float acc = 0.f;
    {
        int d0 = sl * 256;
        #pragma unroll 4
        for (int i = 0; i < 256; i++) {
            int d = d0 + i;
            acc += (g_pool[b * Dsz + d] * inv) * W_enc[d * Hn + h];
        }
    }
    {
        int c0 = sl * 38;
        int c1 = min(c0 + 38, CDn);
        #pragma unroll 2
        for (int c = c0; c < c1; c++)
            acc += concept1[b * CDn + c] * Wc1[c * Hn + h]
                 + concept2[b * CDn + c] * Wc2[c * Hn + h];
    }
    part[sl][h] = acc;
    __syncthreads();
    if (sl == 0) {
        float a = b_enc[h];
        #pragma unroll
        for (int j = 0; j < 8; j++) a += part[j][h];
        video[h] = fmaxf(a, 0.f);
    }
    __syncthreads();
    {
        float a2 = 0.f, a3 = 0.f;
        int k0 = sl * 16;
        #pragma unroll
        for (int i = 0; i < 16; i++) {
            int k = k0 + i;
            float v = video[k];
            a2 += v * Wt1[k * THn + h];
            a3 += v * W3[k * Hn + h];
        }
        part[sl][h] = a2;
        part2[sl][h] = a3;
    }
    __syncthreads();
    if (sl == 0) {
        float a2 = bt1[h], a3 = 0.f;
        #pragma unroll
        for (int j = 0; j < 8; j++) { a2 += part[j][h]; a3 += part2[j][h]; }
        th[h] = fmaxf(a2, 0.f);
        g_vw3[b * Hn + h] = a3;
    }
    __syncthreads();
    if (tid < Tn) {
        float a4 = bt2[tid];
        #pragma unroll 8
        for (int k = 0; k < THn; k++) a4 += th[k] * Wt2[k * Tn + tid];
        logits[tid] = a4;
    }
    __syncthreads();
    if (tid == 0) {
        float m = -1e30f;
        for (int t = 0; t < Tn; t++) m = fmaxf(m, logits[t]);
        float ssum = 0.f;
        for (int t = 0; t < Tn; t++) { float e = __expf(logits[t] - m); logits[t] = e; ssum += e; }
        float invs = 1.f / ssum;
        for (int t = 0; t < Tn; t++) g_probs[b * Tn + t] = logits[t] * invs;
    }
}

// ---------------------------------------------------------------------------
// fp16 hi/lo 2-term GEMM (batch @ W1) + fused topic epilogue.
// BM=128, BN=128, KCH=64, 512 threads (16 warps, 32x32 warp tiles),
// double-buffered, ldmatrix + cp.async.
// ---------------------------------------------------------------------------
#define KCH   64
#define NCHK  (Dsz / KCH)               // 32
#define STAGE 49152                     // Ah 16K | Al 16K | B 16K
#define OFF_AL 16384
#define OFF_B  32768
#define SM_CONTRIB 98304                // 10240 B
#define SM_VW3     108544               // 4096 B
#define SM_B1      112640               // 512 B
#define SM_WOUT    113152               // 512 B
#define SM_PROBS   113664               // 768 B
#define SM_RED     114432               // 8192 B  [128][4][4]
#define SM_BYTES   (122624 + 1024)

__global__ __launch_bounds__(512, 1)
void gemm_tc_kernel(const float* __restrict__ batch,
                    const float* __restrict__ b1,
                    const float* __restrict__ w_out,
                    const float* __restrict__ b_out_p,
                    float* __restrict__ out,
                    int out_size) {
    extern __shared__ char smem_raw[];
    uint32_t sb0 = smem_u32(smem_raw);
    uint32_t sb = (sb0 + 1023) & ~1023u;
    char* smem = smem_raw + (sb - sb0);

    int tid = threadIdx.x;
    int wid = tid >> 5, lane = tid & 31;
    int m0 = blockIdx.x * 128;

    // epilogue-constant preload (covered by first in-loop __syncthreads)
    for (int i = tid; i < Tn * Hn; i += 512)
        ((float*)(smem + SM_CONTRIB))[i] = g_contrib[i];
    for (int i = tid; i < Bsz * Hn; i += 512)
        ((float*)(smem + SM_VW3))[i] = g_vw3[i];
    if (tid < Hn) {
        ((float*)(smem + SM_B1))[tid] = b1[tid];
        ((float*)(smem + SM_WOUT))[tid] = w_out[tid];
    }
    if (tid < Bsz * Tn)
        ((float*)(smem + SM_PROBS))[tid] = g_probs[tid];

    // ---- per-thread A-load mapping: row = tid>>2, 16 floats at (tid&3)*16 ----
    int lrow = tid >> 2;
    int lq = tid & 3;
    const float* aptr = batch + (size_t)(m0 + lrow) * Dsz + lq * 16;
    uint32_t a_sts[2];
    #pragma unroll
    for (int g = 0; g < 2; g++)
        a_sts[g] = (uint32_t)lrow * 128 +
                   (((uint32_t)(lq * 32 + g * 16)) ^ (((uint32_t)lrow & 7) << 4));
    // B cp.async: 2 x 16B per thread per chunk
    int brow_g[2], bc16[2];
    uint32_t b_dst[2];
    #pragma unroll
    for (int j = 0; j < 2; j++) {
        int gid = tid + j * 512;
        brow_g[j] = gid >> 3;
        bc16[j] = gid & 7;
        b_dst[j] = (uint32_t)brow_g[j] * 128 +
                   (((uint32_t)(bc16[j] * 16)) ^ (((uint32_t)brow_g[j] & 7) << 4));
    }

    // ---- per-warp fragment mapping: 16 warps, warp tile 32x32 ----
    int wm = wid >> 2, wn = wid & 3;
    int lr = lane & 7, s1 = (lane >> 3) & 1, s2 = lane >> 4;
    uint32_t a_base[2], a_xor[2];
    #pragma unroll
    for (int mt = 0; mt < 2; mt++) {
        int arow = wm * 32 + mt * 16 + s1 * 8 + lr;
        a_base[mt] = (uint32_t)arow * 128;
        a_xor[mt] = ((uint32_t)arow & 7) << 4;
    }
    uint32_t b_base[2], b_xor[2];
    #pragma unroll
    for (int np = 0; np < 2; np++) {
        int brow = wn * 32 + np * 16 + s2 * 8 + lr;
        b_base[np] = (uint32_t)brow * 128;
        b_xor[np] = ((uint32_t)brow & 7) << 4;
    }
    uint32_t a_kadd = (uint32_t)(s2 * 16);
    uint32_t b_kadd = (uint32_t)(s1 * 16);

    float acc[2][4][4];
    #pragma unroll
    for (int mt = 0; mt < 2; mt++)
        #pragma unroll
        for (int nt = 0; nt < 4; nt++)
            #pragma unroll
            for (int e = 0; e < 4; e++) acc[mt][nt][e] = 0.f;

    // ---- prologue: LDG A chunk0 ; cp.async B chunk0->st0, chunk1->st1 ----
    float4 ar[4];
    #pragma unroll
    for (int g = 0; g < 4; g++) ar[g] = ((const float4*)aptr)[g];
    #pragma unroll
    for (int c = 0; c < 2; c++) {
        uint32_t bB = sb + c * STAGE + OFF_B;
        int k0 = c * KCH;
        #pragma unroll
        for (int j = 0; j < 2; j++)
            CP_ASYNC16(bB + b_dst[j],
                       g_Wh + (size_t)brow_g[j] * Dsz + k0 + bc16[j] * 8);
        CP_COMMIT();
    }

    for (int c = 0; c < NCHK; c++) {
        int p = c & 1;
        if (c == NCHK - 1) { CP_WAIT0(); } else { CP_WAIT1(); }

        // STS A (fp32 -> fp16 hi + residual lo)
        {
            char* bah = smem + p * STAGE;
            char* bal = bah + OFF_AL;
            uint32_t hi[4], lo[4];
            #pragma unroll
            for (int g = 0; g < 2; g++) {
                float4 v0 = ar[2 * g], v1 = ar[2 * g + 1];
                __half h0 = __float2half_rn(v0.x), h1 = __float2half_rn(v0.y);
                __half h2 = __float2half_rn(v0.z), h3 = __float2half_rn(v0.w);
                __half h4 = __float2half_rn(v1.x), h5 = __float2half_rn(v1.y);
                __half h6 = __float2half_rn(v1.z), h7 = __float2half_rn(v1.w);
                hi[0] = packh2(h0, h1); hi[1] = packh2(h2, h3);
                hi[2] = packh2(h4, h5); hi[3] = packh2(h6, h7);
                lo[0] = packh2(__float2half_rn(v0.x - __half2float(h0)),
                               __float2half_rn(v0.y - __half2float(h1)));
                lo[1] = packh2(__float2half_rn(v0.z - __half2float(h2)),
                               __float2half_rn(v0.w - __half2float(h3)));
                lo[2] = packh2(__float2half_rn(v1.x - __half2float(h4)),
                               __float2half_rn(v1.y - __half2float(h5)));
                lo[3] = packh2(__float2half_rn(v1.z - __half2float(h6)),
                               __float2half_rn(v1.w - __half2float(h7)));
                *(uint4*)(bah + a_sts[g]) = make_uint4(hi[0], hi[1], hi[2], hi[3]);
                *(uint4*)(bal + a_sts[g]) = make_uint4(lo[0], lo[1], lo[2], lo[3]);
            }
        }
        __syncthreads();

        // prefetch next A chunk
        if (c + 1 < NCHK) {
            const float4* ap = (const float4*)(aptr + (c + 1) * KCH);
            #pragma unroll
            for (int g = 0; g < 4; g++) ar[g] = ap[g];
        }

        // compute on stage p: 4 k16 steps
        {
            uint32_t Ahb = sb + p * STAGE;
            uint32_t Alb = Ahb + OFF_AL;
            uint32_t Bb  = Ahb + OFF_B;
            #pragma unroll
            for (int ks = 0; ks < 4; ks++) {
                uint32_t ka = (uint32_t)(ks * 32) + a_kadd;
                uint32_t kb = (uint32_t)(ks * 32) + b_kadd;
                uint32_t afh[2][4], afl[2][4];
                #pragma unroll
                for (int mt = 0; mt < 2; mt++) {
                    LDSM4(afh[mt][0], afh[mt][1], afh[mt][2], afh[mt][3],
                          Ahb + a_base[mt] + (ka ^ a_xor[mt]));
                    LDSM4(afl[mt][0], afl[mt][1], afl[mt][2], afl[mt][3],
                          Alb + a_base[mt] + (ka ^ a_xor[mt]));
                }
                uint32_t bf[4][2];
                #pragma unroll
                for (int np = 0; np < 2; np++)
                    LDSM4(bf[2 * np][0], bf[2 * np][1], bf[2 * np + 1][0], bf[2 * np + 1][1],
                          Bb + b_base[np] + (kb ^ b_xor[np]));
                #pragma unroll
                for (int mt = 0; mt < 2; mt++)
                    #pragma unroll
                    for (int nt = 0; nt < 4; nt++) {
                        mma16816h(acc[mt][nt], afh[mt], bf[nt]);
                        mma16816h(acc[mt][nt], afl[mt], bf[nt]);
                    }
            }
        }
        __syncthreads();

        // issue B cp.async for chunk c+2 into stage p
        if (c + 2 < NCHK) {
            uint32_t bB = sb + p * STAGE + OFF_B;
            int k0 = (c + 2) * KCH;
            #pragma unroll
            for (int j = 0; j < 2; j++)
                CP_ASYNC16(bB + b_dst[j],
                           g_Wh + (size_t)brow_g[j] * Dsz + k0 + bc16[j] * 8);
            CP_COMMIT();
        }
    }

    // ----- Epilogue: base = acc + b1 + vw3[b]; 20-topic loop, 4/sync -----
    float* s_red   = (float*)(smem + SM_RED);          // [128][4][4]
    const float* s_vw3  = (const float*)(smem + SM_VW3);
    const float* s_b1v  = (const float*)(smem + SM_B1);
    const float* s_wo   = (const float*)(smem + SM_WOUT);
    const float* s_prob = (const float*)(smem + SM_PROBS);
    const float* s_con  = (const float*)(smem + SM_CONTRIB);
    float bo = b_out_p[0];
    int r = lane >> 2, q = lane & 3;

    #pragma unroll
    for (int mt = 0; mt < 2; mt++) {
        int rg0 = m0 + wm * 32 + mt * 16 + r;
        int rg1 = rg0 + 8;
        int b0 = rg0 / ROWS_PER_B;
        int b1i = rg1 / ROWS_PER_B;
        #pragma unroll
        for (int nt = 0; nt < 4; nt++)
            #pragma unroll
            for (int e = 0; e < 2; e++) {
                int col = wn * 32 + nt * 8 + 2 * q + e;
                acc[mt][nt][e]     += s_b1v[col] + s_vw3[b0 * Hn + col];
                acc[mt][nt][2 + e] += s_b1v[col] + s_vw3[b1i * Hn + col];
            }
    }

    float wv[4][2];
    #pragma unroll
    for (int nt = 0; nt < 4; nt++)
        #pragma unroll
        for (int e = 0; e < 2; e++)
            wv[nt][e] = s_wo[wn * 32 + nt * 8 + 2 * q + e];

    float orow = 0.f;     // per-row accumulator for threads tid<128
    int myrow = m0 + (tid & 127);
    int myb = myrow / ROWS_PER_B;

    for (int tg = 0; tg < 5; tg++) {
        #pragma unroll
        for (int mt = 0; mt < 2; mt++) {
            float p0[4] = {0.f, 0.f, 0.f, 0.f};
            float p1[4] = {0.f, 0.f, 0.f, 0.f};
            #pragma unroll
            for (int tt = 0; tt < 4; tt++) {
                int t = tg * 4 + tt;
                #pragma unroll
                for (int nt = 0; nt < 4; nt++)
                    #pragma unroll
                    for (int e = 0; e < 2; e++) {
                        float cv = s_con[t * Hn + wn * 32 + nt * 8 + 2 * q + e];
                        p0[tt] = fmaf(fmaxf(acc[mt][nt][e]     + cv, 0.f), wv[nt][e], p0[tt]);
                        p1[tt] = fmaf(fmaxf(acc[mt][nt][2 + e] + cv, 0.f), wv[nt][e], p1[tt]);
                    }
            }
            #pragma unroll
            for (int tt = 0; tt < 4; tt++) {
                p0[tt] += __shfl_xor_sync(0xffffffffu, p0[tt], 1);
                p0[tt] += __shfl_xor_sync(0xffffffffu, p0[tt], 2);
                p1[tt] += __shfl_xor_sync(0xffffffffu, p1[tt], 1);
                p1[tt] += __shfl_xor_sync(0xffffffffu, p1[tt], 2);
            }
            if (q == 0) {
                int row0 = wm * 32 + mt * 16 + r;
                #pragma unroll
                for (int tt = 0; tt < 4; tt++) {
                    s_red[(row0 * 4 + wn) * 4 + tt]       = p0[tt];
                    s_red[((row0 + 8) * 4 + wn) * 4 + tt] = p1[tt];
                }
            }
        }
        __syncthreads();
        if (tid < 128) {
            #pragma unroll
            for (int tt = 0; tt < 4; tt++) {
                int t = tg * 4 + tt;
                float s = s_red[(tid * 4 + 0) * 4 + tt] + s_red[(tid * 4 + 1) * 4 + tt]
                        + s_red[(tid * 4 + 2) * 4 + tt] + s_red[(tid * 4 + 3) * 4 + tt] + bo;
                float sig = 1.f / (1.f + __expf(-s));
                float sc = sig * s_prob[myb * Tn + t] - 0.01f;
                orow += fmaxf(sc, 0.f);
            }
        }
        __syncthreads();
    }

    if (tid < 128) {
        float v = orow * (1.f / (float)Tn);
        out[myrow] = v;
        if (out_size >= 2 * Mrows) out[Mrows + myrow] = v;
    }
}

// ---------------------------------------------------------------------------
extern "C" void kernel_launch(void* const* d_in, const int* in_sizes, int n_in,
                              void* d_out, int out_size) {
    const float* batch     = (const float*)d_in[0];
    const int*   seg_len   = (const int*)  d_in[1];
    const float* concept1  = (const float*)d_in[2];
    const float* concept2  = (const float*)d_in[3];
    const float* W_enc     = (const float*)d_in[4];
    const float* b_enc     = (const float*)d_in[5];
    const float* Wc1       = (const float*)d_in[6];
    const float* Wc2       = (const float*)d_in[7];
    const float* Wt1       = (const float*)d_in[8];
    const float* bt1       = (const float*)d_in[9];
    const float* Wt2       = (const float*)d_in[10];
    const float* bt2       = (const float*)d_in[11];
    const float* topic_emb = (const float*)d_in[12];
    const float* W1        = (const float*)d_in[13];
    const float* b1        = (const float*)d_in[14];
    const float* W2        = (const float*)d_in[15];
    const float* W3        = (const float*)d_in[16];
    const float* w_out     = (const float*)d_in[17];
    const float* b_out     = (const float*)d_in[18];
    float* out = (float*)d_out;

    cudaFuncSetAttribute(gemm_tc_kernel,
                         cudaFuncAttributeMaxDynamicSharedMemorySize, SM_BYTES);

    prep_kernel<<<Tn + 64 + (Hn * Dsz) / 256, 256>>>(W1, topic_emb, W2);
    pool_kernel<<<dim3(Dsz / 256, Ssz, Bsz * 4), 256>>>(batch, seg_len);
    small_kernel<<<Bsz, 1024>>>(seg_len, concept1, concept2, W_enc, b_enc,
                                Wc1, Wc2, Wt1, bt1, Wt2, bt2, W3);
    gemm_tc_kernel<<<Mrows / 128, 512, SM_BYTES>>>(batch, b1, w_out, b_out,
                                                   out, out_size);
}

// round 7
// speedup vs baseline: 4.0386x; 1.2139x over previous
#include <cuda_runtime.h>
#include <cuda_fp16.h>
#include <stdint.h>

// Problem constants
#define Bsz 8
#define Ssz 20
#define Fsz 200
#define Dsz 2048
#define Tn  20
#define En  128
#define Hn  128
#define CDn 300
#define THn 128
#define Mrows (Bsz*Ssz*Fsz)     // 32000
#define ROWS_PER_B (Ssz*Fsz)    // 4000

// Scratch (no allocations allowed)
__device__ float g_pool[Bsz*Dsz];
__device__ float g_vw3[Bsz*Hn];
__device__ float g_probs[Bsz*Tn];
__device__ float g_contrib[Tn*Hn];
__device__ __half g_Wh[Hn*Dsz];                   // W1^T fp16  [n][k]

// ---------------------------------------------------------------------------
__device__ __forceinline__ uint32_t smem_u32(const void* p) {
    uint32_t a;
    asm("{ .reg .u64 t; cvta.to.shared.u64 t, %1; cvt.u32.u64 %0, t; }"
        : "=r"(a) : "l"(p));
    return a;
}
__device__ __forceinline__ void mma16816h(float* d, const uint32_t* a, const uint32_t* b) {
    asm volatile(
        "mma.sync.aligned.m16n8k16.row.col.f32.f16.f16.f32 "
        "{%0,%1,%2,%3}, {%4,%5,%6,%7}, {%8,%9}, {%0,%1,%2,%3};"
        : "+f"(d[0]), "+f"(d[1]), "+f"(d[2]), "+f"(d[3])
        : "r"(a[0]), "r"(a[1]), "r"(a[2]), "r"(a[3]), "r"(b[0]), "r"(b[1]));
}
#define LDSM4(r0, r1, r2, r3, addr) \
    asm volatile("ldmatrix.sync.aligned.m8n8.x4.shared.b16 {%0,%1,%2,%3}, [%4];" \
                 : "=r"(r0), "=r"(r1), "=r"(r2), "=r"(r3) : "r"(addr))
#define CP_ASYNC16(dst, src) \
    asm volatile("cp.async.cg.shared.global [%0], [%1], 16;" :: "r"(dst), "l"(src))
#define CP_COMMIT() asm volatile("cp.async.commit_group;")
#define CP_WAIT1()  asm volatile("cp.async.wait_group 1;")
#define CP_WAIT0()  asm volatile("cp.async.wait_group 0;")

__device__ __forceinline__ uint32_t packh2(__half a, __half b) {
    __half2 h = __halves2half2(a, b);
    return *(uint32_t*)&h;
}

// ---------------------------------------------------------------------------
// prep: contrib (blocks 0..19) + zero g_pool (20..83) + coalesced W1
// transpose->fp16 (84..115).  grid 116 x 256
// ---------------------------------------------------------------------------
__global__ void prep_kernel(const float* __restrict__ W1,
                            const float* __restrict__ topic_emb,
                            const float* __restrict__ W2) {
    int bx = blockIdx.x, tid = threadIdx.x;
    if (bx < Tn) {
        __shared__ float red[2][Hn];
        int h = tid & 127, e2 = tid >> 7;
        float acc = 0.f;
        int e0 = e2 * 64;
        #pragma unroll 8
        for (int e = e0; e < e0 + 64; e++)
            acc += topic_emb[bx * En + e] * W2[e * Hn + h];
        red[e2][h] = acc;
        __syncthreads();
        if (e2 == 0) g_contrib[bx * Hn + h] = red[0][h] + red[1][h];
    } else if (bx < Tn + 64) {
        g_pool[(bx - Tn) * 256 + tid] = 0.f;
    } else {
        // coalesced transpose: 64 k-rows x 128 n per block
        __shared__ __half tile[64][132];
        int k0 = (bx - Tn - 64) * 64;
        #pragma unroll
        for (int p = 0; p < 8; p++) {
            int fidx = p * 256 + tid;
            int row = fidx >> 5, c4 = (fidx & 31) * 4;
            float4 v = *(const float4*)(W1 + (size_t)(k0 + row) * Hn + c4);
            tile[row][c4]     = __float2half_rn(v.x);
            tile[row][c4 + 1] = __float2half_rn(v.y);
            tile[row][c4 + 2] = __float2half_rn(v.z);
            tile[row][c4 + 3] = __float2half_rn(v.w);
        }
        __syncthreads();
        int n = tid >> 1, kh = (tid & 1) * 32;
        __half* dst = g_Wh + (size_t)n * Dsz + k0 + kh;
        uint32_t w[16];
        #pragma unroll
        for (int j = 0; j < 16; j++)
            w[j] = packh2(tile[kh + 2 * j][n], tile[kh + 2 * j + 1][n]);
        #pragma unroll
        for (int j = 0; j < 4; j++)
            *(uint4*)(dst + 8 * j) = make_uint4(w[4 * j], w[4 * j + 1],
                                                w[4 * j + 2], w[4 * j + 3]);
    }
}

// grid (8, 20, 32): z = b*4 + f-quarter, 256 threads
__global__ void pool_kernel(const float* __restrict__ batch,
                            const int* __restrict__ seg_len) {
    int b = blockIdx.z >> 2, fq = blockIdx.z & 3, s = blockIdx.y;
    int d = blockIdx.x * 256 + threadIdx.x;
    int len = seg_len[b * Ssz + s];
    int f0 = fq * 50;
    int f1 = min(len, f0 + 50);
    if (f0 >= f1) return;
    const float* p = batch + ((size_t)(b * Ssz + s)) * Fsz * Dsz + d;
    float acc = 0.f;
    #pragma unroll 5
    for (int f = f0; f < f1; f++) acc += p[(size_t)f * Dsz];
    atomicAdd(&g_pool[b * Dsz + d], acc);
}

// grid Bsz blocks, 1024 threads
__global__ void small_kernel(const int* __restrict__ seg_len,
                             const float* __restrict__ concept1,
                             const float* __restrict__ concept2,
                             const float* __restrict__ W_enc,
                             const float* __restrict__ b_enc,
                             const float* __restrict__ Wc1,
                             const float* __restrict__ Wc2,
                             const float* __restrict__ Wt1,
                             const float* __restrict__ bt1,
                             const float* __restrict__ Wt2,
                             const float* __restrict__ bt2,
                             const float* __restrict__ W3) {
    int b = blockIdx.x;
    int tid = threadIdx.x;
    int h  = tid & 127;
    int sl = tid >> 7;
    __shared__ float part[8][Hn];
    __shared__ float part2[8][Hn];
    __shared__ float video[Hn];
    __shared__ float th[THn];
    __shared__ float logits[Tn];

    int cnt = 0;
    for (int s = 0; s < Ssz; s++) cnt += seg_len[b * Ssz + s];
    float inv = 1.f / fmaxf((float)cnt, 1.f);

    float acc = 0.f;
    {
        int d0 = sl * 256;
        #pragma unroll 4
        for (int i = 0; i < 256; i++) {
            int d = d0 + i;
            acc += (g_pool[b * Dsz + d] * inv) * W_enc[d * Hn + h];
        }
    }
    {
        int c0 = sl * 38;
        int c1 = min(c0 + 38, CDn);
        #pragma unroll 2
        for (int c = c0; c < c1; c++)
            acc += concept1[b * CDn + c] * Wc1[c * Hn + h]
                 + concept2[b * CDn + c] * Wc2[c * Hn + h];
    }
    part[sl][h] = acc;
    __syncthreads();
    if (sl == 0) {
        float a = b_enc[h];
        #pragma unroll
        for (int j = 0; j < 8; j++) a += part[j][h];
        video[h] = fmaxf(a, 0.f);
    }
    __syncthreads();
    {
        float a2 = 0.f, a3 = 0.f;
        int k0 = sl * 16;
        #pragma unroll
        for (int i = 0; i < 16; i++) {
            int k = k0 + i;
            float v = video[k];
            a2 += v * Wt1[k * THn + h];
            a3 += v * W3[k * Hn + h];
        }
        part[sl][h] = a2;
        part2[sl][h] = a3;
    }
    __syncthreads();
    if (sl == 0) {
        float a2 = bt1[h], a3 = 0.f;
        #pragma unroll
        for (int j = 0; j < 8; j++) { a2 += part[j][h]; a3 += part2[j][h]; }
        th[h] = fmaxf(a2, 0.f);
        g_vw3[b * Hn + h] = a3;
    }
    __syncthreads();
    if (tid < Tn) {
        float a4 = bt2[tid];
        #pragma unroll 8
        for (int k = 0; k < THn; k++) a4 += th[k] * Wt2[k * Tn + tid];
        logits[tid] = a4;
    }
    __syncthreads();
    if (tid == 0) {
        float m = -1e30f;
        for (int t = 0; t < Tn; t++) m = fmaxf(m, logits[t]);
        float ssum = 0.f;
        for (int t = 0; t < Tn; t++) { float e = __expf(logits[t] - m); logits[t] = e; ssum += e; }
        float invs = 1.f / ssum;
        for (int t = 0; t < Tn; t++) g_probs[b * Tn + t] = logits[t] * invs;
    }
}

// ---------------------------------------------------------------------------
// single-fp16 GEMM (batch @ W1) + fused topic epilogue.
// BM=128, BN=128, KCH=64, 512 threads (16 warps, 32x32 warp tiles),
// double-buffered, ldmatrix + cp.async.
// ---------------------------------------------------------------------------
#define KCH   64
#define NCHK  (Dsz / KCH)               // 32
#define STAGE 32768                     // Ah 16K | B 16K
#define OFF_B  16384
#define SM_CONTRIB 65536                // 10240 B
#define SM_VW3     75776                // 4096 B
#define SM_B1      79872                // 512 B
#define SM_WOUT    80384                // 512 B
#define SM_PROBS   80896                // 768 B
#define SM_RED     81664                // 8192 B  [128][4][4]
#define SM_BYTES   (89856 + 1024)

__global__ __launch_bounds__(512, 1)
void gemm_tc_kernel(const float* __restrict__ batch,
                    const float* __restrict__ b1,
                    const float* __restrict__ w_out,
                    const float* __restrict__ b_out_p,
                    float* __restrict__ out,
                    int out_size) {
    extern __shared__ char smem_raw[];
    uint32_t sb0 = smem_u32(smem_raw);
    uint32_t sb = (sb0 + 1023) & ~1023u;
    char* smem = smem_raw + (sb - sb0);

    int tid = threadIdx.x;
    int wid = tid >> 5, lane = tid & 31;
    int m0 = blockIdx.x * 128;

    // epilogue-constant preload (covered by first in-loop __syncthreads)
    for (int i = tid; i < Tn * Hn; i += 512)
        ((float*)(smem + SM_CONTRIB))[i] = g_contrib[i];
    for (int i = tid; i < Bsz * Hn; i += 512)
        ((float*)(smem + SM_VW3))[i] = g_vw3[i];
    if (tid < Hn) {
        ((float*)(smem + SM_B1))[tid] = b1[tid];
        ((float*)(smem + SM_WOUT))[tid] = w_out[tid];
    }
    if (tid < Bsz * Tn)
        ((float*)(smem + SM_PROBS))[tid] = g_probs[tid];

    // ---- per-thread A-load mapping: row = tid>>2, 16 floats at (tid&3)*16 ----
    int lrow = tid >> 2;
    int lq = tid & 3;
    const float* aptr = batch + (size_t)(m0 + lrow) * Dsz + lq * 16;
    uint32_t a_sts[2];
    #pragma unroll
    for (int g = 0; g < 2; g++)
        a_sts[g] = (uint32_t)lrow * 128 +
                   (((uint32_t)(lq * 32 + g * 16)) ^ (((uint32_t)lrow & 7) << 4));
    // B cp.async: 2 x 16B per thread per chunk
    int brow_g[2], bc16[2];
    uint32_t b_dst[2];
    #pragma unroll
    for (int j = 0; j < 2; j++) {
        int gid = tid + j * 512;
        brow_g[j] = gid >> 3;
        bc16[j] = gid & 7;
        b_dst[j] = (uint32_t)brow_g[j] * 128 +
                   (((uint32_t)(bc16[j] * 16)) ^ (((uint32_t)brow_g[j] & 7) << 4));
    }

    // ---- per-warp fragment mapping: 16 warps, warp tile 32x32 ----
    int wm = wid >> 2, wn = wid & 3;
    int lr = lane & 7, s1 = (lane >> 3) & 1, s2 = lane >> 4;
    uint32_t a_base[2], a_xor[2];
    #pragma unroll
    for (int mt = 0; mt < 2; mt++) {
        int arow = wm * 32 + mt * 16 + s1 * 8 + lr;
        a_base[mt] = (uint32_t)arow * 128;
        a_xor[mt] = ((uint32_t)arow & 7) << 4;
    }
    uint32_t b_base[2], b_xor[2];
    #pragma unroll
    for (int np = 0; np < 2; np++) {
        int brow = wn * 32 + np * 16 + s2 * 8 + lr;
        b_base[np] = (uint32_t)brow * 128;
        b_xor[np] = ((uint32_t)brow & 7) << 4;
    }
    uint32_t a_kadd = (uint32_t)(s2 * 16);
    uint32_t b_kadd = (uint32_t)(s1 * 16);

    float acc[2][4][4];
    #pragma unroll
    for (int mt = 0; mt < 2; mt++)
        #pragma unroll
        for (int nt = 0; nt < 4; nt++)
            #pragma unroll
            for (int e = 0; e < 4; e++) acc[mt][nt][e] = 0.f;

    // ---- prologue: LDG A chunk0 ; cp.async B chunk0->st0, chunk1->st1 ----
    float4 ar[4];
    #pragma unroll
    for (int g = 0; g < 4; g++) ar[g] = ((const float4*)aptr)[g];
    #pragma unroll
    for (int c = 0; c < 2; c++) {
        uint32_t bB = sb + c * STAGE + OFF_B;
        int k0 = c * KCH;
        #pragma unroll
        for (int j = 0; j < 2; j++)
            CP_ASYNC16(bB + b_dst[j],
                       g_Wh + (size_t)brow_g[j] * Dsz + k0 + bc16[j] * 8);
        CP_COMMIT();
    }

    for (int c = 0; c < NCHK; c++) {
        int p = c & 1;
        if (c == NCHK - 1) { CP_WAIT0(); } else { CP_WAIT1(); }

        // STS A (fp32 -> fp16)
        {
            char* bah = smem + p * STAGE;
            uint32_t hi[4];
            #pragma unroll
            for (int g = 0; g < 2; g++) {
                float4 v0 = ar[2 * g], v1 = ar[2 * g + 1];
                hi[0] = packh2(__float2half_rn(v0.x), __float2half_rn(v0.y));
                hi[1] = packh2(__float2half_rn(v0.z), __float2half_rn(v0.w));
                hi[2] = packh2(__float2half_rn(v1.x), __float2half_rn(v1.y));
                hi[3] = packh2(__float2half_rn(v1.z), __float2half_rn(v1.w));
                *(uint4*)(bah + a_sts[g]) = make_uint4(hi[0], hi[1], hi[2], hi[3]);
            }
        }
        __syncthreads();

        // prefetch next A chunk
        if (c + 1 < NCHK) {
            const float4* ap = (const float4*)(aptr + (c + 1) * KCH);
            #pragma unroll
            for (int g = 0; g < 4; g++) ar[g] = ap[g];
        }

        // compute on stage p: 4 k16 steps
        {
            uint32_t Ahb = sb + p * STAGE;
            uint32_t Bb  = Ahb + OFF_B;
            #pragma unroll
            for (int ks = 0; ks < 4; ks++) {
                uint32_t ka = (uint32_t)(ks * 32) + a_kadd;
                uint32_t kb = (uint32_t)(ks * 32) + b_kadd;
                uint32_t af[2][4];
                #pragma unroll
                for (int mt = 0; mt < 2; mt++)
                    LDSM4(af[mt][0], af[mt][1], af[mt][2], af[mt][3],
                          Ahb + a_base[mt] + (ka ^ a_xor[mt]));
                uint32_t bf[4][2];
                #pragma unroll
                for (int np = 0; np < 2; np++)
                    LDSM4(bf[2 * np][0], bf[2 * np][1], bf[2 * np + 1][0], bf[2 * np + 1][1],
                          Bb + b_base[np] + (kb ^ b_xor[np]));
                #pragma unroll
                for (int mt = 0; mt < 2; mt++)
                    #pragma unroll
                    for (int nt = 0; nt < 4; nt++)
                        mma16816h(acc[mt][nt], af[mt], bf[nt]);
            }
        }
        __syncthreads();

        // issue B cp.async for chunk c+2 into stage p
        if (c + 2 < NCHK) {
            uint32_t bB = sb + p * STAGE + OFF_B;
            int k0 = (c + 2) * KCH;
            #pragma unroll
            for (int j = 0; j < 2; j++)
                CP_ASYNC16(bB + b_dst[j],
                           g_Wh + (size_t)brow_g[j] * Dsz + k0 + bc16[j] * 8);
            CP_COMMIT();
        }
    }

    // ----- Epilogue: base = acc + b1 + vw3[b]; 20-topic loop, 4/sync -----
    float* s_red   = (float*)(smem + SM_RED);          // [128][4][4]
    const float* s_vw3  = (const float*)(smem + SM_VW3);
    const float* s_b1v  = (const float*)(smem + SM_B1);
    const float* s_wo   = (const float*)(smem + SM_WOUT);
    const float* s_prob = (const float*)(smem + SM_PROBS);
    const float* s_con  = (const float*)(smem + SM_CONTRIB);
    float bo = b_out_p[0];
    int r = lane >> 2, q = lane & 3;

    #pragma unroll
    for (int mt = 0; mt < 2; mt++) {
        int rg0 = m0 + wm * 32 + mt * 16 + r;
        int rg1 = rg0 + 8;
        int b0 = rg0 / ROWS_PER_B;
        int b1i = rg1 / ROWS_PER_B;
        #pragma unroll
        for (int nt = 0; nt < 4; nt++)
            #pragma unroll
            for (int e = 0; e < 2; e++) {
                int col = wn * 32 + nt * 8 + 2 * q + e;
                acc[mt][nt][e]     += s_b1v[col] + s_vw3[b0 * Hn + col];
                acc[mt][nt][2 + e] += s_b1v[col] + s_vw3[b1i * Hn + col];
            }
    }

    float wv[4][2];
    #pragma unroll
    for (int nt = 0; nt < 4; nt++)
        #pragma unroll
        for (int e = 0; e < 2; e++)
            wv[nt][e] = s_wo[wn * 32 + nt * 8 + 2 * q + e];

    float orow = 0.f;     // per-row accumulator for threads tid<128
    int myrow = m0 + (tid & 127);
    int myb = myrow / ROWS_PER_B;

    for (int tg = 0; tg < 5; tg++) {
        #pragma unroll
        for (int mt = 0; mt < 2; mt++) {
            float p0[4] = {0.f, 0.f, 0.f, 0.f};
            float p1[4] = {0.f, 0.f, 0.f, 0.f};
            #pragma unroll
            for (int tt = 0; tt < 4; tt++) {
                int t = tg * 4 + tt;
                #pragma unroll
                for (int nt = 0; nt < 4; nt++)
                    #pragma unroll
                    for (int e = 0; e < 2; e++) {
                        float cv = s_con[t * Hn + wn * 32 + nt * 8 + 2 * q + e];
                        p0[tt] = fmaf(fmaxf(acc[mt][nt][e]     + cv, 0.f), wv[nt][e], p0[tt]);
                        p1[tt] = fmaf(fmaxf(acc[mt][nt][2 + e] + cv, 0.f), wv[nt][e], p1[tt]);
                    }
            }
            #pragma unroll
            for (int tt = 0; tt < 4; tt++) {
                p0[tt] += __shfl_xor_sync(0xffffffffu, p0[tt], 1);
                p0[tt] += __shfl_xor_sync(0xffffffffu, p0[tt], 2);
                p1[tt] += __shfl_xor_sync(0xffffffffu, p1[tt], 1);
                p1[tt] += __shfl_xor_sync(0xffffffffu, p1[tt], 2);
            }
            if (q == 0) {
                int row0 = wm * 32 + mt * 16 + r;
                #pragma unroll
                for (int tt = 0; tt < 4; tt++) {
                    s_red[(row0 * 4 + wn) * 4 + tt]       = p0[tt];
                    s_red[((row0 + 8) * 4 + wn) * 4 + tt] = p1[tt];
                }
            }
        }
        __syncthreads();
        if (tid < 128) {
            #pragma unroll
            for (int tt = 0; tt < 4; tt++) {
                int t = tg * 4 + tt;
                float s = s_red[(tid * 4 + 0) * 4 + tt] + s_red[(tid * 4 + 1) * 4 + tt]
                        + s_red[(tid * 4 + 2) * 4 + tt] + s_red[(tid * 4 + 3) * 4 + tt] + bo;
                float sig = 1.f / (1.f + __expf(-s));
                float sc = sig * s_prob[myb * Tn + t] - 0.01f;
                orow += fmaxf(sc, 0.f);
            }
        }
        __syncthreads();
    }

    if (tid < 128) {
        float v = orow * (1.f / (float)Tn);
        out[myrow] = v;
        if (out_size >= 2 * Mrows) out[Mrows + myrow] = v;
    }
}

// ---------------------------------------------------------------------------
extern "C" void kernel_launch(void* const* d_in, const int* in_sizes, int n_in,
                              void* d_out, int out_size) {
    const float* batch     = (const float*)d_in[0];
    const int*   seg_len   = (const int*)  d_in[1];
    const float* concept1  = (const float*)d_in[2];
    const float* concept2  = (const float*)d_in[3];
    const float* W_enc     = (const float*)d_in[4];
    const float* b_enc     = (const float*)d_in[5];
    const float* Wc1       = (const float*)d_in[6];
    const float* Wc2       = (const float*)d_in[7];
    const float* Wt1       = (const float*)d_in[8];
    const float* bt1       = (const float*)d_in[9];
    const float* Wt2       = (const float*)d_in[10];
    const float* bt2       = (const float*)d_in[11];
    const float* topic_emb = (const float*)d_in[12];
    const float* W1        = (const float*)d_in[13];
    const float* b1        = (const float*)d_in[14];
    const float* W2        = (const float*)d_in[15];
    const float* W3        = (const float*)d_in[16];
    const float* w_out     = (const float*)d_in[17];
    const float* b_out     = (const float*)d_in[18];
    float* out = (float*)d_out;

    cudaFuncSetAttribute(gemm_tc_kernel,
                         cudaFuncAttributeMaxDynamicSharedMemorySize, SM_BYTES);

    prep_kernel<<<Tn + 64 + 32, 256>>>(W1, topic_emb, W2);
    pool_kernel<<<dim3(Dsz / 256, Ssz, Bsz * 4), 256>>>(batch, seg_len);
    small_kernel<<<Bsz, 1024>>>(seg_len, concept1, concept2, W_enc, b_enc,
                                Wc1, Wc2, Wt1, bt1, Wt2, bt2, W3);
    gemm_tc_kernel<<<Mrows / 128, 512, SM_BYTES>>>(batch, b1, w_out, b_out,
                                                   out, out_size);
}